// round 4
// baseline (speedup 1.0000x reference)
#include <cuda_runtime.h>

#define NJ 24
#define NV 6890
#define JSPLIT 32
#define JCHUNK 216   // ceil(6890/32)

__device__ __constant__ int c_par[NJ] =
    {-1,0,0,0,1,2,3,4,5,6,7,8,9,9,9,12,13,14,16,17,18,19,20,21};

// scratch (no allocations allowed -> __device__ globals)
__device__ float g_part[NJ][JSPLIT][6];  // per-(joint,slice) partial sums
__device__ float g_A[NJ * 12];           // per joint: 3x4 row-major blend matrix

// ---------------------------------------------------------------------------
// Kernel 1: partial joint sums.  grid = (JSPLIT, NJ), block = 128.
// ---------------------------------------------------------------------------
__global__ void __launch_bounds__(128) joints_kernel(
    const float* __restrict__ Jreg,
    const float* __restrict__ shapedirs,
    const float* __restrict__ v_template,
    const float* __restrict__ beta)
{
    const int s = blockIdx.x;
    const int j = blockIdx.y;
    __shared__ float sb[10];
    if (threadIdx.x < 10) sb[threadIdx.x] = beta[threadIdx.x];
    __syncthreads();

    const int v0 = s * JCHUNK;
    const int v1 = min(v0 + JCHUNK, NV);

    float accP0 = 0.f, accP1 = 0.f, accP2 = 0.f;
    float accD0 = 0.f, accD1 = 0.f, accD2 = 0.f;

    for (int v = v0 + threadIdx.x; v < v1; v += 128) {
        float r = Jreg[j * NV + v];
        const float* vt = v_template + v * 3;
        const float* sd = shapedirs + v * 30;   // (v, c, k) -> v*30 + c*10 + k
        float d0 = 0.f, d1 = 0.f, d2 = 0.f;
        #pragma unroll
        for (int k = 0; k < 10; k++) {
            float b = sb[k];
            d0 += sd[k]      * b;
            d1 += sd[10 + k] * b;
            d2 += sd[20 + k] * b;
        }
        float t0 = vt[0], t1 = vt[1], t2 = vt[2];
        accD0 += r * t0;        accD1 += r * t1;        accD2 += r * t2;
        accP0 += r * (t0 + d0); accP1 += r * (t1 + d1); accP2 += r * (t2 + d2);
    }

    __shared__ float red[6][128];
    int t = threadIdx.x;
    red[0][t] = accP0; red[1][t] = accP1; red[2][t] = accP2;
    red[3][t] = accD0; red[4][t] = accD1; red[5][t] = accD2;
    __syncthreads();
    for (int w = 64; w > 0; w >>= 1) {
        if (t < w) {
            #pragma unroll
            for (int q = 0; q < 6; q++) red[q][t] += red[q][t + w];
        }
        __syncthreads();
    }
    if (t < 6) g_part[j][s][t] = red[t][0];
}

// ---------------------------------------------------------------------------
// Kernel 2: build the 24 blend transforms A_j = pose_j @ inv(da_j)
// ---------------------------------------------------------------------------
__device__ __forceinline__ void matmul4(const float* A, const float* B, float* C)
{
    #pragma unroll
    for (int r = 0; r < 4; r++)
        #pragma unroll
        for (int c = 0; c < 4; c++) {
            float s = 0.f;
            #pragma unroll
            for (int k = 0; k < 4; k++) s += A[r * 4 + k] * B[k * 4 + c];
            C[r * 4 + c] = s;
        }
}

__global__ void transforms_kernel(const float* __restrict__ theta,
                                  const float* __restrict__ da_theta)
{
    __shared__ float L[2][NJ][16];
    __shared__ float G[2][NJ][16];
    __shared__ float Jm[2][NJ][3];
    const int tid = threadIdx.x;

    // phase 0: reduce the per-slice partials -> joint locations
    if (tid < 48) {
        int w = tid / NJ;            // 0 = pose, 1 = da (rest)
        int j = tid % NJ;
        float a0 = 0.f, a1 = 0.f, a2 = 0.f;
        #pragma unroll
        for (int s = 0; s < JSPLIT; s++) {
            a0 += g_part[j][s][w * 3 + 0];
            a1 += g_part[j][s][w * 3 + 1];
            a2 += g_part[j][s][w * 3 + 2];
        }
        Jm[w][j][0] = a0; Jm[w][j][1] = a1; Jm[w][j][2] = a2;
    }
    __syncthreads();

    // phase 1: rodrigues + local 4x4
    if (tid < 48) {
        int w = tid / NJ;
        int j = tid % NJ;
        const float* th = (w == 0) ? theta : da_theta;
        float r0 = th[j * 3 + 0], r1 = th[j * 3 + 1], r2 = th[j * 3 + 2];
        float n  = sqrtf(r0 * r0 + r1 * r1 + r2 * r2) + 1e-8f;
        float co = cosf(n), si = sinf(n);
        float u0 = r0 / n, u1 = r1 / n, u2 = r2 / n;
        float omc = 1.0f - co;

        float R00 = co + omc * u0 * u0;
        float R01 = omc * u0 * u1 - si * u2;
        float R02 = omc * u0 * u2 + si * u1;
        float R10 = omc * u1 * u0 + si * u2;
        float R11 = co + omc * u1 * u1;
        float R12 = omc * u1 * u2 - si * u0;
        float R20 = omc * u2 * u0 - si * u1;
        float R21 = omc * u2 * u1 + si * u0;
        float R22 = co + omc * u2 * u2;

        int p = c_par[j];
        float jr0, jr1, jr2;
        if (p < 0) { jr0 = Jm[w][j][0]; jr1 = Jm[w][j][1]; jr2 = Jm[w][j][2]; }
        else {
            jr0 = Jm[w][j][0] - Jm[w][p][0];
            jr1 = Jm[w][j][1] - Jm[w][p][1];
            jr2 = Jm[w][j][2] - Jm[w][p][2];
        }
        float* Lw = &L[w][j][0];
        Lw[0] = R00; Lw[1] = R01; Lw[2]  = R02; Lw[3]  = jr0;
        Lw[4] = R10; Lw[5] = R11; Lw[6]  = R12; Lw[7]  = jr1;
        Lw[8] = R20; Lw[9] = R21; Lw[10] = R22; Lw[11] = jr2;
        Lw[12] = 0.f; Lw[13] = 0.f; Lw[14] = 0.f; Lw[15] = 1.f;
    }
    __syncthreads();

    // phase 2: kinematic chain (two independent serial chains)
    if (tid < 2) {
        int w = tid;
        #pragma unroll
        for (int q = 0; q < 16; q++) G[w][0][q] = L[w][0][q];
        for (int i = 1; i < NJ; i++)
            matmul4(&G[w][c_par[i]][0], &L[w][i][0], &G[w][i][0]);
    }
    __syncthreads();

    // phase 3: pack + rigid inverse + A = pose' @ inv(da')
    if (tid < NJ) {
        int j = tid;
        float Rp[9], tp[3], Rd[9], td[3];
        #pragma unroll
        for (int r = 0; r < 3; r++) {
            #pragma unroll
            for (int c = 0; c < 3; c++) {
                Rp[r * 3 + c] = G[0][j][r * 4 + c];
                Rd[r * 3 + c] = G[1][j][r * 4 + c];
            }
            tp[r] = G[0][j][r * 4 + 3] - (Rp[r*3+0] * Jm[0][j][0] +
                                          Rp[r*3+1] * Jm[0][j][1] +
                                          Rp[r*3+2] * Jm[0][j][2]);
            td[r] = G[1][j][r * 4 + 3] - (Rd[r*3+0] * Jm[1][j][0] +
                                          Rd[r*3+1] * Jm[1][j][1] +
                                          Rd[r*3+2] * Jm[1][j][2]);
        }
        // rigid inverse: inv(da') = [Rd^T | -Rd^T td]; A_R = Rp Rd^T, A_t = tp - A_R td
        #pragma unroll
        for (int r = 0; r < 3; r++) {
            float a0 = Rp[r*3+0]*Rd[0] + Rp[r*3+1]*Rd[1] + Rp[r*3+2]*Rd[2];
            float a1 = Rp[r*3+0]*Rd[3] + Rp[r*3+1]*Rd[4] + Rp[r*3+2]*Rd[5];
            float a2 = Rp[r*3+0]*Rd[6] + Rp[r*3+1]*Rd[7] + Rp[r*3+2]*Rd[8];
            float at = tp[r] - (a0 * td[0] + a1 * td[1] + a2 * td[2]);
            g_A[j * 12 + r * 4 + 0] = a0;
            g_A[j * 12 + r * 4 + 1] = a1;
            g_A[j * 12 + r * 4 + 2] = a2;
            g_A[j * 12 + r * 4 + 3] = at;
        }
    }
}

// ---------------------------------------------------------------------------
// Kernel 3: LBS. 8 points/thread, f32x2 FMAs, LDS.128 coefficient loads.
// ---------------------------------------------------------------------------
typedef unsigned long long u64;

__device__ __forceinline__ u64 pack2(float lo, float hi) {
    u64 d; asm("mov.b64 %0, {%1, %2};" : "=l"(d) : "f"(lo), "f"(hi)); return d;
}
__device__ __forceinline__ u64 fma2(u64 a, u64 b, u64 c) {
    u64 d; asm("fma.rn.f32x2 %0, %1, %2, %3;" : "=l"(d) : "l"(a), "l"(b), "l"(c));
    return d;
}
__device__ __forceinline__ float2 unpack2(u64 v) {
    float lo, hi; asm("mov.b64 {%0, %1}, %2;" : "=f"(lo), "=f"(hi) : "l"(v));
    return make_float2(lo, hi);
}

__global__ void __launch_bounds__(256) lbs_kernel(const float* __restrict__ pts,
                                                  const float* __restrict__ wts,
                                                  float* __restrict__ out,
                                                  int N)
{
    // coefficients duplicated (a,a), packed two-per-16B for LDS.128 loads
    __shared__ __align__(16) ulonglong2 sA[NJ * 6];   // [j*6 + c*2 + h]
    for (int i = threadIdx.x; i < NJ * 6; i += blockDim.x) {
        float a0 = g_A[i * 2 + 0];
        float a1 = g_A[i * 2 + 1];
        ulonglong2 e;
        e.x = pack2(a0, a0);
        e.y = pack2(a1, a1);
        sA[i] = e;
    }
    __syncthreads();

    long long base = ((long long)blockIdx.x * blockDim.x + threadIdx.x) * 8;
    if (base >= N) return;

    if (base + 8 <= N) {
        const float4 xa = *(const float4*)(pts + base);
        const float4 xb = *(const float4*)(pts + base + 4);
        const float4 ya = *(const float4*)(pts + (long long)N + base);
        const float4 yb = *(const float4*)(pts + (long long)N + base + 4);
        const float4 za = *(const float4*)(pts + 2LL * N + base);
        const float4 zb = *(const float4*)(pts + 2LL * N + base + 4);

        u64 xp[4], yp[4], zp[4];
        xp[0] = pack2(xa.x, xa.y); xp[1] = pack2(xa.z, xa.w);
        xp[2] = pack2(xb.x, xb.y); xp[3] = pack2(xb.z, xb.w);
        yp[0] = pack2(ya.x, ya.y); yp[1] = pack2(ya.z, ya.w);
        yp[2] = pack2(yb.x, yb.y); yp[3] = pack2(yb.z, yb.w);
        zp[0] = pack2(za.x, za.y); zp[1] = pack2(za.z, za.w);
        zp[2] = pack2(zb.x, zb.y); zp[3] = pack2(zb.z, zb.w);

        u64 o[3][4];
        #pragma unroll
        for (int c = 0; c < 3; c++)
            #pragma unroll
            for (int p = 0; p < 4; p++) o[c][p] = 0ull;

        #pragma unroll
        for (int j = 0; j < NJ; j++) {
            const float4 wa = *(const float4*)(wts + (long long)j * N + base);
            const float4 wb = *(const float4*)(wts + (long long)j * N + base + 4);
            u64 wp[4];
            wp[0] = pack2(wa.x, wa.y); wp[1] = pack2(wa.z, wa.w);
            wp[2] = pack2(wb.x, wb.y); wp[3] = pack2(wb.z, wb.w);
            #pragma unroll
            for (int c = 0; c < 3; c++) {
                ulonglong2 q0 = sA[j * 6 + c * 2 + 0];   // a0, a1
                ulonglong2 q1 = sA[j * 6 + c * 2 + 1];   // a2, a3
                #pragma unroll
                for (int p = 0; p < 4; p++) {
                    u64 r = fma2(q0.x, xp[p],
                            fma2(q0.y, yp[p],
                            fma2(q1.x, zp[p], q1.y)));
                    o[c][p] = fma2(wp[p], r, o[c][p]);
                }
            }
        }

        #pragma unroll
        for (int c = 0; c < 3; c++) {
            float2 a = unpack2(o[c][0]), b = unpack2(o[c][1]);
            float2 d = unpack2(o[c][2]), e = unpack2(o[c][3]);
            *(float4*)(out + (long long)c * N + base)     = make_float4(a.x, a.y, b.x, b.y);
            *(float4*)(out + (long long)c * N + base + 4) = make_float4(d.x, d.y, e.x, e.y);
        }
    } else {
        // scalar tail
        for (long long n = base; n < N; n++) {
            float x = pts[n], y = pts[(long long)N + n], z = pts[2LL * N + n];
            float o0 = 0.f, o1 = 0.f, o2 = 0.f;
            for (int j = 0; j < NJ; j++) {
                float w = wts[(long long)j * N + n];
                const float* A = &g_A[j * 12];
                o0 += w * (A[0] * x + A[1] * y + A[2]  * z + A[3]);
                o1 += w * (A[4] * x + A[5] * y + A[6]  * z + A[7]);
                o2 += w * (A[8] * x + A[9] * y + A[10] * z + A[11]);
            }
            out[n] = o0;
            out[(long long)N + n] = o1;
            out[2LL * N + n] = o2;
        }
    }
}

// ---------------------------------------------------------------------------
extern "C" void kernel_launch(void* const* d_in, const int* in_sizes, int n_in,
                              void* d_out, int out_size)
{
    const float* pts       = (const float*)d_in[0];  // (3, N)
    const float* wts       = (const float*)d_in[1];  // (24, N)
    const float* beta      = (const float*)d_in[2];  // (10,)
    const float* theta     = (const float*)d_in[3];  // (24, 3)
    const float* da_theta  = (const float*)d_in[4];  // (24, 3)
    const float* shapedirs = (const float*)d_in[5];  // (6890, 3, 10)
    const float* v_templ   = (const float*)d_in[6];  // (6890, 3)
    const float* Jreg      = (const float*)d_in[7];  // (24, 6890)
    float* out = (float*)d_out;                      // (1, 3, N)

    const int N = in_sizes[0] / 3;

    dim3 jgrid(JSPLIT, NJ);
    joints_kernel<<<jgrid, 128>>>(Jreg, shapedirs, v_templ, beta);
    transforms_kernel<<<1, 64>>>(theta, da_theta);

    long long nthreads = ((long long)N + 7) / 8;
    int blocks = (int)((nthreads + 255) / 256);
    lbs_kernel<<<blocks, 256>>>(pts, wts, out, N);
}

// round 5
// speedup vs baseline: 1.4387x; 1.4387x over previous
#include <cuda_runtime.h>

#define NJ 24
#define NV 6890
#define JSPLIT 32
#define JCHUNK 216   // ceil(6890/32)

__device__ __constant__ int c_par[NJ] =
    {-1,0,0,0,1,2,3,4,5,6,7,8,9,9,9,12,13,14,16,17,18,19,20,21};

// scratch (no allocations allowed -> __device__ globals)
__device__ float g_part[NJ][JSPLIT][6];  // per-(joint,slice) partial sums
__device__ float g_A[NJ * 12];           // per joint: 3x4 row-major blend matrix

// ---------------------------------------------------------------------------
// Kernel 1: partial joint sums.  grid = (JSPLIT, NJ), block = 128.
// ---------------------------------------------------------------------------
__global__ void __launch_bounds__(128) joints_kernel(
    const float* __restrict__ Jreg,
    const float* __restrict__ shapedirs,
    const float* __restrict__ v_template,
    const float* __restrict__ beta)
{
    const int s = blockIdx.x;
    const int j = blockIdx.y;
    __shared__ float sb[10];
    if (threadIdx.x < 10) sb[threadIdx.x] = beta[threadIdx.x];
    __syncthreads();

    const int v0 = s * JCHUNK;
    const int v1 = min(v0 + JCHUNK, NV);

    float accP0 = 0.f, accP1 = 0.f, accP2 = 0.f;
    float accD0 = 0.f, accD1 = 0.f, accD2 = 0.f;

    for (int v = v0 + threadIdx.x; v < v1; v += 128) {
        float r = Jreg[j * NV + v];
        const float* vt = v_template + v * 3;
        const float* sd = shapedirs + v * 30;   // (v, c, k) -> v*30 + c*10 + k
        float d0 = 0.f, d1 = 0.f, d2 = 0.f;
        #pragma unroll
        for (int k = 0; k < 10; k++) {
            float b = sb[k];
            d0 += sd[k]      * b;
            d1 += sd[10 + k] * b;
            d2 += sd[20 + k] * b;
        }
        float t0 = vt[0], t1 = vt[1], t2 = vt[2];
        accD0 += r * t0;        accD1 += r * t1;        accD2 += r * t2;
        accP0 += r * (t0 + d0); accP1 += r * (t1 + d1); accP2 += r * (t2 + d2);
    }

    __shared__ float red[6][128];
    int t = threadIdx.x;
    red[0][t] = accP0; red[1][t] = accP1; red[2][t] = accP2;
    red[3][t] = accD0; red[4][t] = accD1; red[5][t] = accD2;
    __syncthreads();
    for (int w = 64; w > 0; w >>= 1) {
        if (t < w) {
            #pragma unroll
            for (int q = 0; q < 6; q++) red[q][t] += red[q][t + w];
        }
        __syncthreads();
    }
    if (t < 6) g_part[j][s][t] = red[t][0];
}

// ---------------------------------------------------------------------------
// Kernel 2: build the 24 blend transforms A_j = pose_j @ inv(da_j)
// ---------------------------------------------------------------------------
__device__ __forceinline__ void matmul4(const float* A, const float* B, float* C)
{
    #pragma unroll
    for (int r = 0; r < 4; r++)
        #pragma unroll
        for (int c = 0; c < 4; c++) {
            float s = 0.f;
            #pragma unroll
            for (int k = 0; k < 4; k++) s += A[r * 4 + k] * B[k * 4 + c];
            C[r * 4 + c] = s;
        }
}

__global__ void transforms_kernel(const float* __restrict__ theta,
                                  const float* __restrict__ da_theta)
{
    __shared__ float L[2][NJ][16];
    __shared__ float G[2][NJ][16];
    __shared__ float Jm[2][NJ][3];
    const int tid = threadIdx.x;

    // phase 0: reduce the per-slice partials -> joint locations
    if (tid < 48) {
        int w = tid / NJ;            // 0 = pose, 1 = da (rest)
        int j = tid % NJ;
        float a0 = 0.f, a1 = 0.f, a2 = 0.f;
        #pragma unroll
        for (int s = 0; s < JSPLIT; s++) {
            a0 += g_part[j][s][w * 3 + 0];
            a1 += g_part[j][s][w * 3 + 1];
            a2 += g_part[j][s][w * 3 + 2];
        }
        Jm[w][j][0] = a0; Jm[w][j][1] = a1; Jm[w][j][2] = a2;
    }
    __syncthreads();

    // phase 1: rodrigues + local 4x4
    if (tid < 48) {
        int w = tid / NJ;
        int j = tid % NJ;
        const float* th = (w == 0) ? theta : da_theta;
        float r0 = th[j * 3 + 0], r1 = th[j * 3 + 1], r2 = th[j * 3 + 2];
        float n  = sqrtf(r0 * r0 + r1 * r1 + r2 * r2) + 1e-8f;
        float co = cosf(n), si = sinf(n);
        float u0 = r0 / n, u1 = r1 / n, u2 = r2 / n;
        float omc = 1.0f - co;

        float R00 = co + omc * u0 * u0;
        float R01 = omc * u0 * u1 - si * u2;
        float R02 = omc * u0 * u2 + si * u1;
        float R10 = omc * u1 * u0 + si * u2;
        float R11 = co + omc * u1 * u1;
        float R12 = omc * u1 * u2 - si * u0;
        float R20 = omc * u2 * u0 - si * u1;
        float R21 = omc * u2 * u1 + si * u0;
        float R22 = co + omc * u2 * u2;

        int p = c_par[j];
        float jr0, jr1, jr2;
        if (p < 0) { jr0 = Jm[w][j][0]; jr1 = Jm[w][j][1]; jr2 = Jm[w][j][2]; }
        else {
            jr0 = Jm[w][j][0] - Jm[w][p][0];
            jr1 = Jm[w][j][1] - Jm[w][p][1];
            jr2 = Jm[w][j][2] - Jm[w][p][2];
        }
        float* Lw = &L[w][j][0];
        Lw[0] = R00; Lw[1] = R01; Lw[2]  = R02; Lw[3]  = jr0;
        Lw[4] = R10; Lw[5] = R11; Lw[6]  = R12; Lw[7]  = jr1;
        Lw[8] = R20; Lw[9] = R21; Lw[10] = R22; Lw[11] = jr2;
        Lw[12] = 0.f; Lw[13] = 0.f; Lw[14] = 0.f; Lw[15] = 1.f;
    }
    __syncthreads();

    // phase 2: kinematic chain (two independent serial chains)
    if (tid < 2) {
        int w = tid;
        #pragma unroll
        for (int q = 0; q < 16; q++) G[w][0][q] = L[w][0][q];
        for (int i = 1; i < NJ; i++)
            matmul4(&G[w][c_par[i]][0], &L[w][i][0], &G[w][i][0]);
    }
    __syncthreads();

    // phase 3: pack + rigid inverse + A = pose' @ inv(da')
    if (tid < NJ) {
        int j = tid;
        float Rp[9], tp[3], Rd[9], td[3];
        #pragma unroll
        for (int r = 0; r < 3; r++) {
            #pragma unroll
            for (int c = 0; c < 3; c++) {
                Rp[r * 3 + c] = G[0][j][r * 4 + c];
                Rd[r * 3 + c] = G[1][j][r * 4 + c];
            }
            tp[r] = G[0][j][r * 4 + 3] - (Rp[r*3+0] * Jm[0][j][0] +
                                          Rp[r*3+1] * Jm[0][j][1] +
                                          Rp[r*3+2] * Jm[0][j][2]);
            td[r] = G[1][j][r * 4 + 3] - (Rd[r*3+0] * Jm[1][j][0] +
                                          Rd[r*3+1] * Jm[1][j][1] +
                                          Rd[r*3+2] * Jm[1][j][2]);
        }
        // rigid inverse: inv(da') = [Rd^T | -Rd^T td]; A_R = Rp Rd^T, A_t = tp - A_R td
        #pragma unroll
        for (int r = 0; r < 3; r++) {
            float a0 = Rp[r*3+0]*Rd[0] + Rp[r*3+1]*Rd[1] + Rp[r*3+2]*Rd[2];
            float a1 = Rp[r*3+0]*Rd[3] + Rp[r*3+1]*Rd[4] + Rp[r*3+2]*Rd[5];
            float a2 = Rp[r*3+0]*Rd[6] + Rp[r*3+1]*Rd[7] + Rp[r*3+2]*Rd[8];
            float at = tp[r] - (a0 * td[0] + a1 * td[1] + a2 * td[2]);
            g_A[j * 12 + r * 4 + 0] = a0;
            g_A[j * 12 + r * 4 + 1] = a1;
            g_A[j * 12 + r * 4 + 2] = a2;
            g_A[j * 12 + r * 4 + 3] = at;
        }
    }
}

// ---------------------------------------------------------------------------
// Kernel 3: LBS. 4 points/thread, f32x2 FMAs, LDS.128 coefficient loads,
// high occupancy (128 threads, min 8 blocks/SM -> <=64 regs).
// ---------------------------------------------------------------------------
typedef unsigned long long u64;

__device__ __forceinline__ u64 pack2(float lo, float hi) {
    u64 d; asm("mov.b64 %0, {%1, %2};" : "=l"(d) : "f"(lo), "f"(hi)); return d;
}
__device__ __forceinline__ u64 fma2(u64 a, u64 b, u64 c) {
    u64 d; asm("fma.rn.f32x2 %0, %1, %2, %3;" : "=l"(d) : "l"(a), "l"(b), "l"(c));
    return d;
}
__device__ __forceinline__ float2 unpack2(u64 v) {
    float lo, hi; asm("mov.b64 {%0, %1}, %2;" : "=f"(lo), "=f"(hi) : "l"(v));
    return make_float2(lo, hi);
}

__global__ void __launch_bounds__(128, 8) lbs_kernel(const float* __restrict__ pts,
                                                     const float* __restrict__ wts,
                                                     float* __restrict__ out,
                                                     int N)
{
    // coefficients duplicated (a,a), packed two-per-16B for LDS.128 loads
    __shared__ __align__(16) ulonglong2 sA[NJ * 6];   // [j*6 + c*2 + h]
    for (int i = threadIdx.x; i < NJ * 6; i += blockDim.x) {
        float a0 = g_A[i * 2 + 0];
        float a1 = g_A[i * 2 + 1];
        ulonglong2 e;
        e.x = pack2(a0, a0);
        e.y = pack2(a1, a1);
        sA[i] = e;
    }
    __syncthreads();

    long long base = ((long long)blockIdx.x * blockDim.x + threadIdx.x) * 4;
    if (base >= N) return;

    if (base + 4 <= N) {
        const float4 x4 = __ldcs((const float4*)(pts + base));
        const float4 y4 = __ldcs((const float4*)(pts + (long long)N + base));
        const float4 z4 = __ldcs((const float4*)(pts + 2LL * N + base));

        u64 x01 = pack2(x4.x, x4.y), x23 = pack2(x4.z, x4.w);
        u64 y01 = pack2(y4.x, y4.y), y23 = pack2(y4.z, y4.w);
        u64 z01 = pack2(z4.x, z4.y), z23 = pack2(z4.z, z4.w);

        u64 o01[3], o23[3];
        #pragma unroll
        for (int c = 0; c < 3; c++) { o01[c] = 0ull; o23[c] = 0ull; }

        #pragma unroll
        for (int j = 0; j < NJ; j++) {
            const float4 wv = __ldcs((const float4*)(wts + (long long)j * N + base));
            u64 w01 = pack2(wv.x, wv.y);
            u64 w23 = pack2(wv.z, wv.w);
            #pragma unroll
            for (int c = 0; c < 3; c++) {
                ulonglong2 q0 = sA[j * 6 + c * 2 + 0];   // (a0,a0),(a1,a1)
                ulonglong2 q1 = sA[j * 6 + c * 2 + 1];   // (a2,a2),(a3,a3)
                u64 r01 = fma2(q0.x, x01, fma2(q0.y, y01, fma2(q1.x, z01, q1.y)));
                u64 r23 = fma2(q0.x, x23, fma2(q0.y, y23, fma2(q1.x, z23, q1.y)));
                o01[c] = fma2(w01, r01, o01[c]);
                o23[c] = fma2(w23, r23, o23[c]);
            }
        }

        #pragma unroll
        for (int c = 0; c < 3; c++) {
            float2 a = unpack2(o01[c]), b = unpack2(o23[c]);
            __stcs((float4*)(out + (long long)c * N + base),
                   make_float4(a.x, a.y, b.x, b.y));
        }
    } else {
        // scalar tail
        for (long long n = base; n < N; n++) {
            float x = pts[n], y = pts[(long long)N + n], z = pts[2LL * N + n];
            float o0 = 0.f, o1 = 0.f, o2 = 0.f;
            for (int j = 0; j < NJ; j++) {
                float w = wts[(long long)j * N + n];
                const float* A = &g_A[j * 12];
                o0 += w * (A[0] * x + A[1] * y + A[2]  * z + A[3]);
                o1 += w * (A[4] * x + A[5] * y + A[6]  * z + A[7]);
                o2 += w * (A[8] * x + A[9] * y + A[10] * z + A[11]);
            }
            out[n] = o0;
            out[(long long)N + n] = o1;
            out[2LL * N + n] = o2;
        }
    }
}

// ---------------------------------------------------------------------------
extern "C" void kernel_launch(void* const* d_in, const int* in_sizes, int n_in,
                              void* d_out, int out_size)
{
    const float* pts       = (const float*)d_in[0];  // (3, N)
    const float* wts       = (const float*)d_in[1];  // (24, N)
    const float* beta      = (const float*)d_in[2];  // (10,)
    const float* theta     = (const float*)d_in[3];  // (24, 3)
    const float* da_theta  = (const float*)d_in[4];  // (24, 3)
    const float* shapedirs = (const float*)d_in[5];  // (6890, 3, 10)
    const float* v_templ   = (const float*)d_in[6];  // (6890, 3)
    const float* Jreg      = (const float*)d_in[7];  // (24, 6890)
    float* out = (float*)d_out;                      // (1, 3, N)

    const int N = in_sizes[0] / 3;

    dim3 jgrid(JSPLIT, NJ);
    joints_kernel<<<jgrid, 128>>>(Jreg, shapedirs, v_templ, beta);
    transforms_kernel<<<1, 64>>>(theta, da_theta);

    long long nthreads = ((long long)N + 3) / 4;
    int blocks = (int)((nthreads + 127) / 128);
    lbs_kernel<<<blocks, 128>>>(pts, wts, out, N);
}